// round 15
// baseline (speedup 1.0000x reference)
#include <cuda_runtime.h>
#include <cuda_fp16.h>
#include <cstdint>

#define B_   32
#define C_   128
#define L_   4096
#define P_   100
#define Q_   20
#define LG   256            // l per block
#define NLG  (L_ / LG)      // 16
#define NCH  2              // 128-l chunks per block
#define NG   (NLG * NCH)    // 32 store groups per (b,p)
#define NBLK (B_ * NLG)     // 512 blocks, all resident in one wave (<=592)
#define NFIN 100            // finalize blocks (100*32 groups = 3200 = B*P)

#define SM_TOTAL 32768      // fp16 tile only: [c(128)][l(128)] swizzled

// chunk scratch: [b][p(128)][w5(5)][g(32)] packed byte HISTOGRAM counters
__device__ unsigned g_chunk[B_ * 128 * 5 * NG];
__device__ int g_sync1;     // arrival counter (zero-init; self-resetting)
__device__ int g_sync2;     // finalize-completion counter

__device__ __forceinline__ unsigned smem_u32(const void* p) {
    unsigned a;
    asm("{ .reg .u64 t; cvta.to.shared.u64 t, %1; cvt.u32.u64 %0, t; }" : "=r"(a) : "l"(p));
    return a;
}
#define LDSM_T(r0, r1, r2, r3, a) \
    asm volatile("ldmatrix.sync.aligned.m8n8.x4.trans.shared.b16 {%0,%1,%2,%3}, [%4];" \
                 : "=r"(r0), "=r"(r1), "=r"(r2), "=r"(r3) : "r"(a))
#define MMA_F16(Cv, Af, b0_, b1_) \
    asm volatile("mma.sync.aligned.m16n8k16.row.col.f32.f16.f16.f32 " \
                 "{%0,%1,%2,%3}, {%4,%5,%6,%7}, {%8,%9}, {%0,%1,%2,%3};" \
                 : "+f"((Cv)[0]), "+f"((Cv)[1]), "+f"((Cv)[2]), "+f"((Cv)[3]) \
                 : "r"((Af).x), "r"((Af).y), "r"((Af).z), "r"((Af).w), "r"(b0_), "r"(b1_))

__device__ __forceinline__ unsigned h2bits(__half2 h) { return *(unsigned*)&h; }

__device__ __forceinline__ unsigned long long shl64_clamp(unsigned long long v, unsigned sh) {
    unsigned long long r;
    asm("shl.b64 %0, %1, %2;" : "=l"(r) : "l"(v), "r"(sh));
    return r;
}
__device__ __forceinline__ unsigned shl32_clamp(unsigned v, unsigned sh) {
    unsigned r;
    asm("shl.b32 %0, %1, %2;" : "=r"(r) : "r"(v), "r"(sh));
    return r;
}

// One-hot histogram add; shl clamping gives double-sided bin clamp for free.
__device__ __forceinline__ void hist_add(float a, float s, float bc, unsigned* acc) {
    float g = fmaxf(fmaf(a, s, bc), -0.5f);
    unsigned j8 = (__float_as_uint(__fadd_rn(g, 12582912.0f)) & 63u) << 3;
    unsigned long long m01 = shl64_clamp(1ull, j8);
    unsigned long long m23 = shl64_clamp(1ull, j8 - 64u);
    unsigned m4 = shl32_clamp(1u, j8 - 128u);
    acc[0] += (unsigned)m01; acc[1] += (unsigned)(m01 >> 32);
    acc[2] += (unsigned)m23; acc[3] += (unsigned)(m23 >> 32);
    acc[4] += m4;
}

// ---------------------------------------------------------------------------
extern __shared__ __align__(16) char smem[];

__global__ __launch_bounds__(256, 4)
void radon_hmma(const float* __restrict__ X,
                const float* __restrict__ W,
                const float* __restrict__ minv,
                const float* __restrict__ maxv,
                float* __restrict__ out) {
    const int tid = threadIdx.x, w = tid >> 5, lane = tid & 31;
    const int b = blockIdx.x >> 4, lg = blockIdx.x & 15;
    const unsigned sXh = smem_u32(smem);

    const bool wactive = (w < 7);     // warp 7: all-pad p rows
    const bool p1active = (w < 6);    // warp 6's p1 rows: all pad

    const int r0 = w * 16 + (lane >> 2);
    const int r1 = r0 + 8;
    const int kp0 = 2 * (lane & 3);
    uint4 Ahi[8];
    if (wactive) {
#pragma unroll
        for (int s = 0; s < 8; s++) {
            int kp = s * 16 + kp0;
            float2 a00 = (r0 < P_) ? *(const float2*)(W + r0 * C_ + kp)     : make_float2(0.f, 0.f);
            float2 a10 = (r1 < P_) ? *(const float2*)(W + r1 * C_ + kp)     : make_float2(0.f, 0.f);
            float2 a01 = (r0 < P_) ? *(const float2*)(W + r0 * C_ + kp + 8) : make_float2(0.f, 0.f);
            float2 a11 = (r1 < P_) ? *(const float2*)(W + r1 * C_ + kp + 8) : make_float2(0.f, 0.f);
            Ahi[s].x = h2bits(__float22half2_rn(a00));
            Ahi[s].y = h2bits(__float22half2_rn(a10));
            Ahi[s].z = h2bits(__float22half2_rn(a01));
            Ahi[s].w = h2bits(__float22half2_rn(a11));
        }
    }

    const int p0 = r0, p1 = r1;
    float s0 = 0.f, c0b = 0.f, s1 = 0.f, c1b = 0.f;
    if (p0 < P_) { float mn = minv[p0]; s0 = 21.0f / (maxv[p0] - mn); c0b = -mn * s0 - 0.5f; }
    if (p1 < P_) { float mn = minv[p1]; s1 = 21.0f / (maxv[p1] - mn); c1b = -mn * s1 - 0.5f; }

    const int rr = lane & 15;
    const unsigned colb0 = (unsigned)((lane >> 4) * 16);
    const float* Xb = X + (size_t)b * C_ * L_ + lg * LG;

    for (int ch = 0; ch < NCH; ch++) {
        unsigned acc0[5] = {0, 0, 0, 0, 0}, acc1[5] = {0, 0, 0, 0, 0};

        const float* Xc = Xb + ch * 128;
#pragma unroll 4
        for (int it = 0; it < 16; it++) {
            int lin = it * 256 + tid;
            int c = lin >> 5, l4 = lin & 31;
            float4 v = *(const float4*)(Xc + (size_t)c * L_ + 4 * l4);
            __half2 h01 = __float22half2_rn(make_float2(v.x, v.y));
            __half2 h23 = __float22half2_rn(make_float2(v.z, v.w));
            unsigned off = (unsigned)(c * 256) + (((unsigned)(l4 * 8)) ^ (((unsigned)c & 7u) << 4));
            *(uint2*)(smem + off) = make_uint2(h2bits(h01), h2bits(h23));
        }
        __syncthreads();

        if (wactive) {
            for (int nt2 = 0; nt2 < 8; nt2++) {
                float C0[4] = {0.f, 0.f, 0.f, 0.f}, C1[4] = {0.f, 0.f, 0.f, 0.f};
                const unsigned colb = colb0 + (unsigned)(nt2 * 32);
#pragma unroll
                for (int s = 0; s < 8; s++) {
                    int cc = s * 16 + rr;
                    unsigned ba = (unsigned)(cc * 256) + (colb ^ (((unsigned)cc & 7u) << 4));
                    unsigned b0, b1, b2, b3;
                    LDSM_T(b0, b1, b2, b3, sXh + ba);
                    MMA_F16(C0, Ahi[s], b0, b1);
                    MMA_F16(C1, Ahi[s], b2, b3);
                }
                hist_add(C0[0], s0, c0b, acc0);
                hist_add(C0[1], s0, c0b, acc0);
                hist_add(C1[0], s0, c0b, acc0);
                hist_add(C1[1], s0, c0b, acc0);
                if (p1active) {
                    hist_add(C0[2], s1, c1b, acc1);
                    hist_add(C0[3], s1, c1b, acc1);
                    hist_add(C1[2], s1, c1b, acc1);
                    hist_add(C1[3], s1, c1b, acc1);
                }
            }
        }
        __syncthreads();

        if (wactive) {
#pragma unroll
            for (int k = 0; k < 5; k++) {
                acc0[k] += __shfl_xor_sync(0xFFFFFFFFu, acc0[k], 1);
                acc0[k] += __shfl_xor_sync(0xFFFFFFFFu, acc0[k], 2);
            }
            if (p1active) {
#pragma unroll
                for (int k = 0; k < 5; k++) {
                    acc1[k] += __shfl_xor_sync(0xFFFFFFFFu, acc1[k], 1);
                    acc1[k] += __shfl_xor_sync(0xFFFFFFFFu, acc1[k], 2);
                }
            }
            if ((lane & 3) == 0) {
                int g = lg * NCH + ch;
                if (p0 < P_) {
                    unsigned* d = g_chunk + ((size_t)(b * 128 + p0) * 5) * NG + g;
#pragma unroll
                    for (int k = 0; k < 5; k++) d[k * NG] = acc0[k];
                }
                if (p1 < P_) {
                    unsigned* d = g_chunk + ((size_t)(b * 128 + p1) * 5) * NG + g;
#pragma unroll
                    for (int k = 0; k < 5; k++) d[k * NG] = acc1[k];
                }
            }
        }
    }

    // ---- fused finalize: grid-wide sync (all 512 blocks resident, one wave) ----
    __syncthreads();
    if (tid == 0) {
        __threadfence();                        // release g_chunk stores
        atomicAdd(&g_sync1, 1);
    }
    if (blockIdx.x < NFIN) {
        if (tid == 0) {
            while (atomicAdd(&g_sync1, 0) < NBLK) { __nanosleep(128); }
        }
        __syncthreads();
        __threadfence();                        // acquire

        int gid = blockIdx.x * 32 + (tid >> 3);
        int k = tid & 7;
        int fb = gid / P_, fp = gid % P_;

        unsigned s01 = 0, s23 = 0;
        if (k < 5) {
            const uint4* src = (const uint4*)(g_chunk + ((size_t)(fb * 128 + fp) * 5 + k) * NG);
#pragma unroll
            for (int i = 0; i < 8; i++) {
                uint4 v = src[i];
                s01 += (v.x & 0x00FF00FFu) + (v.y & 0x00FF00FFu) + (v.z & 0x00FF00FFu) + (v.w & 0x00FF00FFu);
                s23 += ((v.x >> 8) & 0x00FF00FFu) + ((v.y >> 8) & 0x00FF00FFu) +
                       ((v.z >> 8) & 0x00FF00FFu) + ((v.w >> 8) & 0x00FF00FFu);
            }
        }
        unsigned h0 = s01 & 0xFFFFu, h1 = s23 & 0xFFFFu, h2 = s01 >> 16, h3 = s23 >> 16;
        unsigned F0 = h0, F1 = F0 + h1, F2 = F1 + h2, F3 = F2 + h3;
        unsigned T = F3;

        unsigned sc = T;
#pragma unroll
        for (int d = 1; d < 8; d <<= 1) {
            unsigned o = __shfl_up_sync(0xFFFFFFFFu, sc, d, 8);
            if ((tid & 7) >= d) sc += o;
        }
        unsigned off = sc - T;

        if (k < 5) {
            const float inv = 1.0f / (float)L_;
            float4 o4;
            o4.x = (float)(off + F0) * inv;
            o4.y = (float)(off + F1) * inv;
            o4.z = (float)(off + F2) * inv;
            o4.w = (float)(off + F3) * inv;
            *(float4*)(out + (size_t)fb * (P_ * Q_) + fp * Q_ + 4 * k) = o4;
        }

        __syncthreads();
        if (tid == 0) {
            int t2 = atomicAdd(&g_sync2, 1);
            if (t2 == NFIN - 1) {               // last finalizer resets for next replay
                atomicExch(&g_sync1, 0);
                atomicExch(&g_sync2, 0);
            }
        }
    }
}

// ---------------------------------------------------------------------------
extern "C" void kernel_launch(void* const* d_in, const int* in_sizes, int n_in,
                              void* d_out, int out_size) {
    const float* X    = (const float*)d_in[0];
    const float* W    = (const float*)d_in[1];
    const float* minv = (const float*)d_in[2];
    const float* maxv = (const float*)d_in[3];
    float* out = (float*)d_out;

    cudaFuncSetAttribute(radon_hmma, cudaFuncAttributeMaxDynamicSharedMemorySize, SM_TOTAL);

    radon_hmma<<<NBLK, 256, SM_TOTAL>>>(X, W, minv, maxv, out);
}

// round 16
// speedup vs baseline: 1.5295x; 1.5295x over previous
#include <cuda_runtime.h>
#include <cuda_fp16.h>
#include <cstdint>

#define B_   32
#define C_   128
#define L_   4096
#define P_   100
#define Q_   20
#define LG   256            // l per block
#define NLG  (L_ / LG)      // 16
#define NCH  2              // 128-l chunks per block
#define NG   (NLG * NCH)    // 32 store groups per (b,p)

#define SM_TOTAL 32768      // fp16 tile only: [c(128)][l(128)] swizzled

// chunk scratch: [b][p(128)][w5(5)][g(32)] packed byte HISTOGRAM counters
__device__ unsigned g_chunk[B_ * 128 * 5 * NG];

__device__ __forceinline__ unsigned smem_u32(const void* p) {
    unsigned a;
    asm("{ .reg .u64 t; cvta.to.shared.u64 t, %1; cvt.u32.u64 %0, t; }" : "=r"(a) : "l"(p));
    return a;
}
#define LDSM_T(r0, r1, r2, r3, a) \
    asm volatile("ldmatrix.sync.aligned.m8n8.x4.trans.shared.b16 {%0,%1,%2,%3}, [%4];" \
                 : "=r"(r0), "=r"(r1), "=r"(r2), "=r"(r3) : "r"(a))
#define MMA_F16(Cv, Af, b0_, b1_) \
    asm volatile("mma.sync.aligned.m16n8k16.row.col.f32.f16.f16.f32 " \
                 "{%0,%1,%2,%3}, {%4,%5,%6,%7}, {%8,%9}, {%0,%1,%2,%3};" \
                 : "+f"((Cv)[0]), "+f"((Cv)[1]), "+f"((Cv)[2]), "+f"((Cv)[3]) \
                 : "r"((Af).x), "r"((Af).y), "r"((Af).z), "r"((Af).w), "r"(b0_), "r"(b1_))

__device__ __forceinline__ unsigned h2bits(__half2 h) { return *(unsigned*)&h; }

// clamped shifts: PTX shl clamps amounts >= width to 0; unsigned wrap of
// negative deltas also lands >= width -> 0. Double-sided bin clamp for free.
__device__ __forceinline__ unsigned long long shl64_clamp(unsigned long long v, unsigned sh) {
    unsigned long long r;
    asm("shl.b64 %0, %1, %2;" : "=l"(r) : "l"(v), "r"(sh));
    return r;
}
__device__ __forceinline__ unsigned shl32_clamp(unsigned v, unsigned sh) {
    unsigned r;
    asm("shl.b32 %0, %1, %2;" : "=r"(r) : "r"(v), "r"(sh));
    return r;
}

// One-hot histogram add: bin j = floor(max((a-mn)*s, -0.5..)); byte j gets +1.
// j in [21,63] (a >= max) shifts past all words -> contributes 0.
__device__ __forceinline__ void hist_add(float a, float s, float bc, unsigned* acc) {
    float g = fmaxf(fmaf(a, s, bc), -0.5f);
    unsigned j8 = (__float_as_uint(__fadd_rn(g, 12582912.0f)) & 63u) << 3;
    unsigned long long m01 = shl64_clamp(1ull, j8);
    unsigned long long m23 = shl64_clamp(1ull, j8 - 64u);
    unsigned m4 = shl32_clamp(1u, j8 - 128u);
    acc[0] += (unsigned)m01; acc[1] += (unsigned)(m01 >> 32);
    acc[2] += (unsigned)m23; acc[3] += (unsigned)(m23 >> 32);
    acc[4] += m4;
}

// ---------------------------------------------------------------------------
extern __shared__ __align__(16) char smem[];

__global__ __launch_bounds__(256, 4)
void radon_hmma(const float* __restrict__ X,
                const float* __restrict__ W,
                const float* __restrict__ minv,
                const float* __restrict__ maxv) {
    const int tid = threadIdx.x, w = tid >> 5, lane = tid & 31;
    const int b = blockIdx.x >> 4, lg = blockIdx.x & 15;
    const unsigned sXh = smem_u32(smem);

    const bool wactive = (w < 7);     // warp 7: all-pad p rows
    const bool p1active = (w < 6);    // warp 6's p1 rows: all pad

    const int r0 = w * 16 + (lane >> 2);
    const int r1 = r0 + 8;
    const int kp0 = 2 * (lane & 3);
    uint4 Ahi[8];
    if (wactive) {
#pragma unroll
        for (int s = 0; s < 8; s++) {
            int kp = s * 16 + kp0;
            float2 a00 = (r0 < P_) ? *(const float2*)(W + r0 * C_ + kp)     : make_float2(0.f, 0.f);
            float2 a10 = (r1 < P_) ? *(const float2*)(W + r1 * C_ + kp)     : make_float2(0.f, 0.f);
            float2 a01 = (r0 < P_) ? *(const float2*)(W + r0 * C_ + kp + 8) : make_float2(0.f, 0.f);
            float2 a11 = (r1 < P_) ? *(const float2*)(W + r1 * C_ + kp + 8) : make_float2(0.f, 0.f);
            Ahi[s].x = h2bits(__float22half2_rn(a00));
            Ahi[s].y = h2bits(__float22half2_rn(a10));
            Ahi[s].z = h2bits(__float22half2_rn(a01));
            Ahi[s].w = h2bits(__float22half2_rn(a11));
        }
    }

    const int p0 = r0, p1 = r1;
    float s0 = 0.f, c0b = 0.f, s1 = 0.f, c1b = 0.f;
    if (p0 < P_) { float mn = minv[p0]; s0 = 21.0f / (maxv[p0] - mn); c0b = -mn * s0 - 0.5f; }
    if (p1 < P_) { float mn = minv[p1]; s1 = 21.0f / (maxv[p1] - mn); c1b = -mn * s1 - 0.5f; }

    const int rr = lane & 15;
    const unsigned colb0 = (unsigned)((lane >> 4) * 16);
    const float* Xb = X + (size_t)b * C_ * L_ + lg * LG;

    for (int ch = 0; ch < NCH; ch++) {
        unsigned acc0[5] = {0, 0, 0, 0, 0}, acc1[5] = {0, 0, 0, 0, 0};

        // convert X chunk fp32 -> fp16; FULL unroll: 16 LDG.128 batched (MLP 16)
        const float* Xc = Xb + ch * 128;
#pragma unroll 16
        for (int it = 0; it < 16; it++) {
            int lin = it * 256 + tid;
            int c = lin >> 5, l4 = lin & 31;
            float4 v = *(const float4*)(Xc + (size_t)c * L_ + 4 * l4);
            __half2 h01 = __float22half2_rn(make_float2(v.x, v.y));
            __half2 h23 = __float22half2_rn(make_float2(v.z, v.w));
            unsigned off = (unsigned)(c * 256) + (((unsigned)(l4 * 8)) ^ (((unsigned)c & 7u) << 4));
            *(uint2*)(smem + off) = make_uint2(h2bits(h01), h2bits(h23));
        }
        __syncthreads();

        if (wactive) {
            for (int nt2 = 0; nt2 < 8; nt2++) {
                float C0[4] = {0.f, 0.f, 0.f, 0.f}, C1[4] = {0.f, 0.f, 0.f, 0.f};
                const unsigned colb = colb0 + (unsigned)(nt2 * 32);
#pragma unroll
                for (int s = 0; s < 8; s++) {
                    int cc = s * 16 + rr;
                    unsigned ba = (unsigned)(cc * 256) + (colb ^ (((unsigned)cc & 7u) << 4));
                    unsigned b0, b1, b2, b3;
                    LDSM_T(b0, b1, b2, b3, sXh + ba);
                    MMA_F16(C0, Ahi[s], b0, b1);
                    MMA_F16(C1, Ahi[s], b2, b3);
                }
                hist_add(C0[0], s0, c0b, acc0);
                hist_add(C0[1], s0, c0b, acc0);
                hist_add(C1[0], s0, c0b, acc0);
                hist_add(C1[1], s0, c0b, acc0);
                if (p1active) {
                    hist_add(C0[2], s1, c1b, acc1);
                    hist_add(C0[3], s1, c1b, acc1);
                    hist_add(C1[2], s1, c1b, acc1);
                    hist_add(C1[3], s1, c1b, acc1);
                }
            }
        }
        __syncthreads();  // mainloop done before next conversion overwrites smem

        if (wactive) {
#pragma unroll
            for (int k = 0; k < 5; k++) {
                acc0[k] += __shfl_xor_sync(0xFFFFFFFFu, acc0[k], 1);
                acc0[k] += __shfl_xor_sync(0xFFFFFFFFu, acc0[k], 2);
            }
            if (p1active) {
#pragma unroll
                for (int k = 0; k < 5; k++) {
                    acc1[k] += __shfl_xor_sync(0xFFFFFFFFu, acc1[k], 1);
                    acc1[k] += __shfl_xor_sync(0xFFFFFFFFu, acc1[k], 2);
                }
            }
            if ((lane & 3) == 0) {
                int g = lg * NCH + ch;
                if (p0 < P_) {
                    unsigned* d = g_chunk + ((size_t)(b * 128 + p0) * 5) * NG + g;
#pragma unroll
                    for (int k = 0; k < 5; k++) d[k * NG] = acc0[k];
                }
                if (p1 < P_) {
                    unsigned* d = g_chunk + ((size_t)(b * 128 + p1) * 5) * NG + g;
#pragma unroll
                    for (int k = 0; k < 5; k++) d[k * NG] = acc1[k];
                }
            }
        }
    }
}

// ---------------------------------------------------------------------------
// Finalize: 8-lane group per (b,p); lane k<5 sums word k over 32 groups (SIMD
// byte-lanes), then shfl-scan converts histogram -> CDF.
__global__ void finalize_kernel(float* __restrict__ out) {
    int t = blockIdx.x * 256 + threadIdx.x;
    int gid = t >> 3, k = t & 7;
    int b = gid / P_, p = gid % P_;

    unsigned s01 = 0, s23 = 0;
    if (k < 5) {
        const uint4* src = (const uint4*)(g_chunk + ((size_t)(b * 128 + p) * 5 + k) * NG);
#pragma unroll
        for (int i = 0; i < 8; i++) {
            uint4 v = src[i];
            s01 += (v.x & 0x00FF00FFu) + (v.y & 0x00FF00FFu) + (v.z & 0x00FF00FFu) + (v.w & 0x00FF00FFu);
            s23 += ((v.x >> 8) & 0x00FF00FFu) + ((v.y >> 8) & 0x00FF00FFu) +
                   ((v.z >> 8) & 0x00FF00FFu) + ((v.w >> 8) & 0x00FF00FFu);
        }
    }
    unsigned h0 = s01 & 0xFFFFu, h1 = s23 & 0xFFFFu, h2 = s01 >> 16, h3 = s23 >> 16;
    unsigned P0 = h0, P1 = P0 + h1, P2 = P1 + h2, P3 = P2 + h3;
    unsigned T = P3;

    unsigned sc = T;
#pragma unroll
    for (int d = 1; d < 8; d <<= 1) {
        unsigned o = __shfl_up_sync(0xFFFFFFFFu, sc, d, 8);
        if ((threadIdx.x & 7) >= d) sc += o;
    }
    unsigned off = sc - T;

    if (k < 5) {
        const float inv = 1.0f / (float)L_;
        float4 o4;
        o4.x = (float)(off + P0) * inv;
        o4.y = (float)(off + P1) * inv;
        o4.z = (float)(off + P2) * inv;
        o4.w = (float)(off + P3) * inv;
        *(float4*)(out + (size_t)b * (P_ * Q_) + p * Q_ + 4 * k) = o4;
    }
}

// ---------------------------------------------------------------------------
extern "C" void kernel_launch(void* const* d_in, const int* in_sizes, int n_in,
                              void* d_out, int out_size) {
    const float* X    = (const float*)d_in[0];
    const float* W    = (const float*)d_in[1];
    const float* minv = (const float*)d_in[2];
    const float* maxv = (const float*)d_in[3];
    float* out = (float*)d_out;

    cudaFuncSetAttribute(radon_hmma, cudaFuncAttributeMaxDynamicSharedMemorySize, SM_TOTAL);

    radon_hmma<<<B_ * NLG, 256, SM_TOTAL>>>(X, W, minv, maxv);
    finalize_kernel<<<(B_ * P_ * 8) / 256, 256>>>(out);
}